// round 6
// baseline (speedup 1.0000x reference)
#include <cuda_runtime.h>

// Problem constants: B=2048, F=P*N=4096, C=10
#define F        4096
#define C        10
#define WPREP_T  256
#define NWARP    (WPREP_T / 32)

// lse geometry
#define TX       128                 // threads over f
#define TY       4                   // row groups
#define LTHREADS (TX * TY)           // 512
#define RG       2                   // rows per thread
#define ROWS     (TY * RG)           // 8 rows per block -> grid 256
#define FT       512                 // f-tile
#define NTILES   (F / FT)            // 8
#define TILE_F4  (C * FT / 4)        // 1280 float4 per tile (20KB)

__device__ float g_pt[C * F];        // pt[c*F + f] = exp(weight[c,f])
__device__ float g_lz[C];            // lz[c] = log(sum_f exp(weight[c,f]))

// ---------- packed f32x2 helpers (FFMA2 only reachable via PTX) ----------
__device__ __forceinline__ unsigned long long pack2(float lo, float hi) {
    unsigned long long r;
    asm("mov.b64 %0, {%1, %2};" : "=l"(r) : "f"(lo), "f"(hi));
    return r;
}
__device__ __forceinline__ void unpack2(unsigned long long v, float& lo, float& hi) {
    asm("mov.b64 {%0, %1}, %2;" : "=f"(lo), "=f"(hi) : "l"(v));
}
__device__ __forceinline__ unsigned long long fma2(unsigned long long a,
                                                   unsigned long long b,
                                                   unsigned long long c) {
    unsigned long long d;
    asm("fma.rn.f32x2 %0, %1, %2, %3;" : "=l"(d) : "l"(a), "l"(b), "l"(c));
    return d;
}
// ---------- cp.async helpers ----------
__device__ __forceinline__ void cp_async16(unsigned int saddr, const void* gptr) {
    asm volatile("cp.async.cg.shared.global [%0], [%1], 16;" :: "r"(saddr), "l"(gptr));
}
__device__ __forceinline__ void cp_commit() {
    asm volatile("cp.async.commit_group;" ::: "memory");
}
__device__ __forceinline__ void cp_wait_all() {
    asm volatile("cp.async.wait_group 0;" ::: "memory");
}

// Kernel 1: exp(weight) transposed-to-[c][f] (identity layout) + row log-sums.
__global__ void wprep_kernel(const float* __restrict__ w) {
    const int c   = blockIdx.x;
    const int tid = threadIdx.x;
    float sum = 0.f;
    for (int f = tid; f < F; f += WPREP_T) {
        float v = __expf(w[c * F + f]);
        g_pt[c * F + f] = v;
        sum += v;
    }
    __shared__ float sred[NWARP];
    #pragma unroll
    for (int o = 16; o > 0; o >>= 1) sum += __shfl_xor_sync(0xffffffffu, sum, o);
    if ((tid & 31) == 0) sred[tid >> 5] = sum;
    __syncthreads();
    if (tid == 0) {
        float t = 0.f;
        #pragma unroll
        for (int i = 0; i < NWARP; i++) t += sred[i];
        g_lz[c] = logf(t);
    }
}

// Kernel 2: out[b,c] = log( sum_f exp(x[b,f]) * pt[c,f] ) - lz[c]
// 512 threads (tx=128 over f, ty=4), RG=2 rows/thread -> 8 rows/block, 256 blocks.
// pt double-buffered into smem via cp.async; inner product in f32x2 (even/odd-f
// partial sums packed in one b64 accumulator), combined at the end.
__global__ __launch_bounds__(LTHREADS, 2) void lse_kernel(const float* __restrict__ x,
                                                          float* __restrict__ out) {
    __shared__ float4 s_pt[2][TILE_F4];          // 2 x 20KB
    __shared__ float s_red[LTHREADS / 32][RG * C];

    const int tid = threadIdx.x;
    const int tx  = tid & (TX - 1);
    const int ty  = tid >> 7;
    const int b0  = blockIdx.x * ROWS + ty * RG;

    unsigned long long acc2[RG][C];
    #pragma unroll
    for (int r = 0; r < RG; r++)
        #pragma unroll
        for (int c = 0; c < C; c++) acc2[r][c] = 0ull;   // bits of (0.f,0.f)

    const float4* gpt4 = reinterpret_cast<const float4*>(g_pt);
    const unsigned int s_base0 = (unsigned int)__cvta_generic_to_shared(&s_pt[0][0]);
    const unsigned int s_base1 = (unsigned int)__cvta_generic_to_shared(&s_pt[1][0]);

    // Prologue: stage tile 0.
    #pragma unroll
    for (int k = 0; k < 3; k++) {
        const int u = tid + k * LTHREADS;
        if (u < TILE_F4) {
            const int c = u >> 7, i = u & 127;           // 128 float4 per c-plane
            cp_async16(s_base0 + (unsigned)u * 16u,
                       gpt4 + ((size_t)c * (F / 4) + i));
        }
    }
    cp_commit();

    const float* xrow0 = x + (size_t)b0 * F;
    const float* xrow1 = x + (size_t)(b0 + 1) * F;

    for (int t = 0; t < NTILES; t++) {
        cp_wait_all();
        __syncthreads();    // tile t visible to all; all done computing tile t-1

        // Stage tile t+1 into the other buffer (runs behind this tile's compute).
        if (t + 1 < NTILES) {
            const unsigned int sb = ((t + 1) & 1) ? s_base1 : s_base0;
            #pragma unroll
            for (int k = 0; k < 3; k++) {
                const int u = tid + k * LTHREADS;
                if (u < TILE_F4) {
                    const int c = u >> 7, i = u & 127;
                    cp_async16(sb + (unsigned)u * 16u,
                               gpt4 + ((size_t)c * (F / 4) + (t + 1) * (FT / 4) + i));
                }
            }
            cp_commit();
        } else {
            cp_commit();    // keep group counts uniform for the final wait
        }

        // Compute tile t.
        const int fbase = t * FT + tx * 4;
        const float4 xv0 = *reinterpret_cast<const float4*>(xrow0 + fbase);
        const float4 xv1 = *reinterpret_cast<const float4*>(xrow1 + fbase);
        const unsigned long long e0a = pack2(__expf(xv0.x), __expf(xv0.y));
        const unsigned long long e0b = pack2(__expf(xv0.z), __expf(xv0.w));
        const unsigned long long e1a = pack2(__expf(xv1.x), __expf(xv1.y));
        const unsigned long long e1b = pack2(__expf(xv1.z), __expf(xv1.w));

        const ulonglong2* sp2 = reinterpret_cast<const ulonglong2*>(&s_pt[t & 1][0]) + tx;
        #pragma unroll
        for (int c = 0; c < C; c++) {
            const ulonglong2 pv = sp2[c * (FT / 4)];     // floats [c*FT + tx*4 .. +3]
            acc2[0][c] = fma2(e0a, pv.x, acc2[0][c]);
            acc2[0][c] = fma2(e0b, pv.y, acc2[0][c]);
            acc2[1][c] = fma2(e1a, pv.x, acc2[1][c]);
            acc2[1][c] = fma2(e1b, pv.y, acc2[1][c]);
        }
    }

    // Combine even/odd-f partials, then reduce over tx (4 warps per ty).
    float accf[RG][C];
    #pragma unroll
    for (int r = 0; r < RG; r++)
        #pragma unroll
        for (int c = 0; c < C; c++) {
            float lo, hi;
            unpack2(acc2[r][c], lo, hi);
            float v = lo + hi;
            #pragma unroll
            for (int o = 16; o > 0; o >>= 1) v += __shfl_xor_sync(0xffffffffu, v, o);
            accf[r][c] = v;
        }

    const int warp = tid >> 5, lane = tid & 31;
    if (lane == 0) {
        #pragma unroll
        for (int r = 0; r < RG; r++)
            #pragma unroll
            for (int c = 0; c < C; c++)
                s_red[warp][r * C + c] = accf[r][c];
    }
    __syncthreads();

    if (tid < ROWS * C) {                                // 80 threads
        const int row = tid / C, c = tid % C;
        const int tyo = row / RG, r = row % RG;
        float s = 0.f;
        #pragma unroll
        for (int wi = 0; wi < TX / 32; wi++)
            s += s_red[tyo * (TX / 32) + wi][r * C + c];
        out[(size_t)(blockIdx.x * ROWS + row) * C + c] = logf(s) - g_lz[c];
    }
}

extern "C" void kernel_launch(void* const* d_in, const int* in_sizes, int n_in,
                              void* d_out, int out_size) {
    const float* x = (const float*)d_in[0];   // (2048, 64, 64) fp32
    const float* w = (const float*)d_in[1];   // (10, 4096) fp32
    float* out = (float*)d_out;               // (2048, 10) fp32

    const int B = in_sizes[0] / F;            // 2048

    wprep_kernel<<<C, WPREP_T>>>(w);
    lse_kernel<<<B / ROWS, LTHREADS>>>(x, out);
}

// round 7
// speedup vs baseline: 1.0828x; 1.0828x over previous
#include <cuda_runtime.h>

// Problem constants: B=2048, F=P*N=4096, C=10
#define F        4096
#define C        10
#define WPREP_T  256
#define NWARP    (WPREP_T / 32)

// lse geometry: one fat CTA per SM, pt fully resident in smem.
#define TX       256                  // threads over f
#define TY       4                    // row groups
#define LTHREADS (TX * TY)            // 1024
#define RG       4                    // rows per thread
#define ROWS     (TY * RG)            // 16 rows per block -> grid 128
#define NCHUNK   (F / (TX * 2))       // 8 (2 f per thread per chunk)
#define REDW     (LTHREADS / 32)      // 32 warps
#define SMEM_FLOATS (C * F + REDW * RG * C)
#define SMEM_BYTES  (SMEM_FLOATS * 4) // 168,960 B < 227KB cap

__device__ float g_pt[C * F];         // pt[c*F + f] = exp(weight[c,f])
__device__ float g_lz[C];             // lz[c] = log(sum_f exp(weight[c,f]))

// Kernel 1: exp(weight) + per-row log-sum. 10 blocks, tiny.
__global__ void wprep_kernel(const float* __restrict__ w) {
    const int c   = blockIdx.x;
    const int tid = threadIdx.x;
    float sum = 0.f;
    for (int f = tid; f < F; f += WPREP_T) {
        float v = __expf(w[c * F + f]);
        g_pt[c * F + f] = v;
        sum += v;
    }
    __shared__ float sred[NWARP];
    #pragma unroll
    for (int o = 16; o > 0; o >>= 1) sum += __shfl_xor_sync(0xffffffffu, sum, o);
    if ((tid & 31) == 0) sred[tid >> 5] = sum;
    __syncthreads();
    if (tid == 0) {
        float t = 0.f;
        #pragma unroll
        for (int i = 0; i < NWARP; i++) t += sred[i];
        g_lz[c] = logf(t);
    }
}

// Kernel 2: out[b,c] = log( sum_f exp(x[b,f]) * pt[c,f] ) - lz[c]
// 1024 threads (tx=256 over f, ty=4), RG=4 rows/thread -> 16 rows/block.
// Entire pt (160KB) loaded to smem once; main loop is sync-free.
__global__ __launch_bounds__(LTHREADS, 1) void lse_kernel(const float* __restrict__ x,
                                                          float* __restrict__ out) {
    extern __shared__ float s[];
    float* s_pt  = s;                 // C*F floats
    float* s_red = s + C * F;         // REDW x (RG*C)

    const int tid = threadIdx.x;
    const int tx  = tid & (TX - 1);
    const int ty  = tid >> 8;         // tid / TX
    const int b0  = blockIdx.x * ROWS + ty * RG;

    // Stage pt once: 10240 float4, 1024 threads -> 10 each, coalesced.
    {
        float4* s4 = reinterpret_cast<float4*>(s_pt);
        const float4* g4 = reinterpret_cast<const float4*>(g_pt);
        #pragma unroll
        for (int k = 0; k < (C * F / 4) / LTHREADS; k++)
            s4[tid + k * LTHREADS] = g4[tid + k * LTHREADS];
    }
    __syncthreads();   // the only sync before the reduction

    float acc[RG][C];
    #pragma unroll
    for (int r = 0; r < RG; r++)
        #pragma unroll
        for (int c = 0; c < C; c++) acc[r][c] = 0.f;

    const float* xbase = x + (size_t)b0 * F;

    #pragma unroll
    for (int ch = 0; ch < NCHUNK; ch++) {
        const int f = ch * (TX * 2) + tx * 2;

        float2 xv[RG];
        #pragma unroll
        for (int r = 0; r < RG; r++)
            xv[r] = *reinterpret_cast<const float2*>(xbase + r * F + f);

        float e[RG][2];
        #pragma unroll
        for (int r = 0; r < RG; r++) {
            e[r][0] = __expf(xv[r].x);
            e[r][1] = __expf(xv[r].y);
        }

        #pragma unroll
        for (int c = 0; c < C; c++) {
            const float2 pv = *reinterpret_cast<const float2*>(s_pt + c * F + f);
            #pragma unroll
            for (int r = 0; r < RG; r++) {
                float a = acc[r][c];
                a = fmaf(e[r][0], pv.x, a);
                a = fmaf(e[r][1], pv.y, a);
                acc[r][c] = a;
            }
        }
    }

    // Reduce over tx: warp shuffles, then smem across the 8 warps of each ty.
    #pragma unroll
    for (int r = 0; r < RG; r++)
        #pragma unroll
        for (int c = 0; c < C; c++) {
            float v = acc[r][c];
            #pragma unroll
            for (int o = 16; o > 0; o >>= 1) v += __shfl_xor_sync(0xffffffffu, v, o);
            acc[r][c] = v;
        }

    const int warp = tid >> 5, lane = tid & 31;
    if (lane == 0) {
        #pragma unroll
        for (int r = 0; r < RG; r++)
            #pragma unroll
            for (int c = 0; c < C; c++)
                s_red[warp * (RG * C) + r * C + c] = acc[r][c];
    }
    __syncthreads();

    if (tid < ROWS * C) {                       // 160 threads
        const int row = tid / C, c = tid % C;
        const int tyo = row / RG, r = row % RG;
        float sm = 0.f;
        #pragma unroll
        for (int wi = 0; wi < TX / 32; wi++)
            sm += s_red[(tyo * (TX / 32) + wi) * (RG * C) + r * C + c];
        out[(size_t)(blockIdx.x * ROWS + row) * C + c] = logf(sm) - g_lz[c];
    }
}

extern "C" void kernel_launch(void* const* d_in, const int* in_sizes, int n_in,
                              void* d_out, int out_size) {
    const float* x = (const float*)d_in[0];   // (2048, 64, 64) fp32
    const float* w = (const float*)d_in[1];   // (10, 4096) fp32
    float* out = (float*)d_out;               // (2048, 10) fp32

    const int B = in_sizes[0] / F;            // 2048

    // Opt into >48KB dynamic smem (attribute set, not an allocation; idempotent).
    cudaFuncSetAttribute(lse_kernel, cudaFuncAttributeMaxDynamicSharedMemorySize,
                         SMEM_BYTES);

    wprep_kernel<<<C, WPREP_T>>>(w);
    lse_kernel<<<B / ROWS, LTHREADS, SMEM_BYTES>>>(x, out);
}

// round 8
// speedup vs baseline: 1.3414x; 1.2388x over previous
#include <cuda_runtime.h>

// Problem constants: B=2048, F=P*N=4096, C=10
#define F        4096
#define C        10

// wprep geometry: 80 blocks = (c, seg), each covers 512 f.
#define WSEG     8
#define WPREP_T  256
#define WF       (F / WSEG)           // 512 f per block
#define NWARP    (WPREP_T / 32)

// lse geometry: one 1024-thread CTA per SM, pt fully smem-resident.
#define TX       128                  // threads over f
#define TY       8                    // row groups
#define LTHREADS (TX * TY)            // 1024
#define RG       2                    // rows per thread
#define ROWS     (TY * RG)            // 16 rows per block -> grid 128
#define FPT      4                    // f per thread per chunk (LDG.128)
#define NCHUNK   (F / (TX * FPT))     // 8
#define REDW     (LTHREADS / 32)      // 32 warps
#define SMEM_BYTES (C * F * 4)        // 160KB dynamic (pt)

__device__ float g_pt[C * F];         // pt[c*F + f] = exp(weight[c,f])
__device__ float g_ps[C * WSEG];      // partial sums of exp(weight[c,:]) per segment

// ---------- packed f32x2 helpers (FFMA2 only reachable via PTX) ----------
__device__ __forceinline__ unsigned long long pack2(float lo, float hi) {
    unsigned long long r;
    asm("mov.b64 %0, {%1, %2};" : "=l"(r) : "f"(lo), "f"(hi));
    return r;
}
__device__ __forceinline__ void unpack2(unsigned long long v, float& lo, float& hi) {
    asm("mov.b64 {%0, %1}, %2;" : "=f"(lo), "=f"(hi) : "l"(v));
}
__device__ __forceinline__ unsigned long long fma2(unsigned long long a,
                                                   unsigned long long b,
                                                   unsigned long long c) {
    unsigned long long d;
    asm("fma.rn.f32x2 %0, %1, %2, %3;" : "=l"(d) : "l"(a), "l"(b), "l"(c));
    return d;
}

// Kernel 1: exp(weight) + segment partial sums. 80 blocks, wide and fast.
__global__ void wprep_kernel(const float* __restrict__ w) {
    const int c   = blockIdx.x >> 3;
    const int seg = blockIdx.x & 7;
    const int tid = threadIdx.x;
    const int f   = seg * WF + tid * 2;

    const float2 wv = *reinterpret_cast<const float2*>(w + (size_t)c * F + f);
    const float e0 = __expf(wv.x), e1 = __expf(wv.y);
    *reinterpret_cast<float2*>(g_pt + (size_t)c * F + f) = make_float2(e0, e1);

    float sum = e0 + e1;
    __shared__ float sred[NWARP];
    #pragma unroll
    for (int o = 16; o > 0; o >>= 1) sum += __shfl_xor_sync(0xffffffffu, sum, o);
    if ((tid & 31) == 0) sred[tid >> 5] = sum;
    __syncthreads();
    if (tid == 0) {
        float t = 0.f;
        #pragma unroll
        for (int i = 0; i < NWARP; i++) t += sred[i];
        g_ps[c * WSEG + seg] = t;
    }
}

// Kernel 2: out[b,c] = log( sum_f exp(x[b,f]) * pt[c,f] ) - log(sum_f pt[c,f])
// 1024 threads (tx=128 over f, ty=8), RG=2 rows/thread -> 16 rows/block.
// pt staged once to smem; mainloop sync-free; inner product in packed f32x2.
__global__ __launch_bounds__(LTHREADS, 1) void lse_kernel(const float* __restrict__ x,
                                                          float* __restrict__ out) {
    extern __shared__ float s_pt[];                     // C*F floats
    __shared__ float s_red[REDW][RG * C];

    const int tid = threadIdx.x;
    const int tx  = tid & (TX - 1);
    const int ty  = tid >> 7;
    const int b0  = blockIdx.x * ROWS + ty * RG;

    // Stage pt once: 10240 float4, 1024 threads -> 10 each, coalesced.
    {
        float4* s4 = reinterpret_cast<float4*>(s_pt);
        const float4* g4 = reinterpret_cast<const float4*>(g_pt);
        #pragma unroll
        for (int k = 0; k < (C * F / 4) / LTHREADS; k++)
            s4[tid + k * LTHREADS] = g4[tid + k * LTHREADS];
    }
    __syncthreads();   // the only sync before the reduction

    unsigned long long acc2[RG][C];
    #pragma unroll
    for (int r = 0; r < RG; r++)
        #pragma unroll
        for (int c = 0; c < C; c++) acc2[r][c] = 0ull;  // bits of (0.f, 0.f)

    const float* xr0 = x + (size_t)b0 * F;
    const float* xr1 = xr0 + F;

    #pragma unroll
    for (int ch = 0; ch < NCHUNK; ch++) {
        const int f = ch * (TX * FPT) + tx * FPT;

        const float4 xa = *reinterpret_cast<const float4*>(xr0 + f);
        const float4 xb = *reinterpret_cast<const float4*>(xr1 + f);

        const unsigned long long e0a = pack2(__expf(xa.x), __expf(xa.y));
        const unsigned long long e0b = pack2(__expf(xa.z), __expf(xa.w));
        const unsigned long long e1a = pack2(__expf(xb.x), __expf(xb.y));
        const unsigned long long e1b = pack2(__expf(xb.z), __expf(xb.w));

        #pragma unroll
        for (int c = 0; c < C; c++) {
            const ulonglong2 pv =
                *reinterpret_cast<const ulonglong2*>(s_pt + c * F + f);
            acc2[0][c] = fma2(e0a, pv.x, acc2[0][c]);
            acc2[0][c] = fma2(e0b, pv.y, acc2[0][c]);
            acc2[1][c] = fma2(e1a, pv.x, acc2[1][c]);
            acc2[1][c] = fma2(e1b, pv.y, acc2[1][c]);
        }
    }

    // Combine packed halves; reduce over tx (4 warps per ty group).
    #pragma unroll
    for (int r = 0; r < RG; r++)
        #pragma unroll
        for (int c = 0; c < C; c++) {
            float lo, hi;
            unpack2(acc2[r][c], lo, hi);
            float v = lo + hi;
            #pragma unroll
            for (int o = 16; o > 0; o >>= 1) v += __shfl_xor_sync(0xffffffffu, v, o);
            if ((tid & 31) == 0) s_red[tid >> 5][r * C + c] = v;
        }
    __syncthreads();

    if (tid < ROWS * C) {                                // 160 threads
        const int row = tid / C, c = tid % C;
        const int tyo = row / RG, r = row % RG;
        float s = 0.f;
        #pragma unroll
        for (int wi = 0; wi < TX / 32; wi++)
            s += s_red[tyo * (TX / 32) + wi][r * C + c];
        float z = 0.f;
        #pragma unroll
        for (int k = 0; k < WSEG; k++) z += g_ps[c * WSEG + k];
        out[(size_t)(blockIdx.x * ROWS + row) * C + c] = logf(s) - logf(z);
    }
}

extern "C" void kernel_launch(void* const* d_in, const int* in_sizes, int n_in,
                              void* d_out, int out_size) {
    const float* x = (const float*)d_in[0];   // (2048, 64, 64) fp32
    const float* w = (const float*)d_in[1];   // (10, 4096) fp32
    float* out = (float*)d_out;               // (2048, 10) fp32

    const int B = in_sizes[0] / F;            // 2048

    // Opt into >48KB dynamic smem (attribute set, not an allocation; idempotent).
    cudaFuncSetAttribute(lse_kernel, cudaFuncAttributeMaxDynamicSharedMemorySize,
                         SMEM_BYTES);

    wprep_kernel<<<C * WSEG, WPREP_T>>>(w);
    lse_kernel<<<B / ROWS, LTHREADS, SMEM_BYTES>>>(x, out);
}